// round 12
// baseline (speedup 1.0000x reference)
#include <cuda_runtime.h>
#include <cuda_bf16.h>
#include <cstdint>
#include <math.h>

// ---------------- problem constants ----------------
#define BATCH 2
#define TT    2048
#define DD    2048
#define HH    16
#define DH    128
#define DKV   512
#define DQ    1024
#define DR    64
#define DQK   192            // DH + DR
#define NTOK  (BATCH*TT)     // 4096
#define BHZ   (BATCH*HH)     // 32
#define EPS   1e-6f
#define SCALE 0.072168783648703220563f   // 1/sqrt(192)

typedef __nv_bfloat16 bf16;

// ---------------- weight arena offsets (elements) ----------------
#define OFF_DQ  0L
#define OFF_UQ  2097152L
#define OFF_QR  4194304L
#define OFF_DKV 5242880L
#define OFF_UK  6291456L
#define OFF_UV  7340032L
#define OFF_O   8388608L
#define W_TOTAL 12582912L

// ---------------- scratch (device globals; allocation-free) ----------------
__device__ __align__(16) float g_cQ  [(size_t)NTOK * DQ];          // fp32 pre-norm
__device__ __align__(16) float g_cKV [(size_t)NTOK * DKV];
__device__ __align__(16) float g_qf  [(size_t)NTOK * HH * DQK];    // fp32 rope staging
__device__ __align__(16) float g_kR  [(size_t)NTOK * DR];
__device__ __align__(16) float g_sc  [(size_t)BHZ * TT * TT];      // fp32 scores

__device__ __align__(16) bf16 g_xh  [(size_t)NTOK * DD];
__device__ __align__(16) bf16 g_xl  [(size_t)NTOK * DD];
__device__ __align__(16) bf16 g_wh  [W_TOTAL];
__device__ __align__(16) bf16 g_wl  [W_TOTAL];
__device__ __align__(16) bf16 g_cQh [(size_t)NTOK * DQ];
__device__ __align__(16) bf16 g_cQl [(size_t)NTOK * DQ];
__device__ __align__(16) bf16 g_cKVh[(size_t)NTOK * DKV];
__device__ __align__(16) bf16 g_cKVl[(size_t)NTOK * DKV];
__device__ __align__(16) bf16 g_qh  [(size_t)NTOK * HH * DQK];
__device__ __align__(16) bf16 g_ql  [(size_t)NTOK * HH * DQK];
__device__ __align__(16) bf16 g_kh  [(size_t)NTOK * HH * DQK];
__device__ __align__(16) bf16 g_kl  [(size_t)NTOK * HH * DQK];
__device__ __align__(16) bf16 g_vh  [(size_t)NTOK * HH * DH];
__device__ __align__(16) bf16 g_vl  [(size_t)NTOK * HH * DH];
__device__ __align__(16) bf16 g_ph  [(size_t)BHZ * TT * TT];
__device__ __align__(16) bf16 g_pl  [(size_t)BHZ * TT * TT];
__device__ __align__(16) bf16 g_aoh [(size_t)NTOK * HH * DH];
__device__ __align__(16) bf16 g_aol [(size_t)NTOK * HH * DH];

// =====================================================================
// helpers
// =====================================================================
#define ASTR 40     // smem row stride (bf16) for Mx32 tiles
#define BSTR 136    // smem row stride (bf16) for 32x128 tiles

__device__ __forceinline__ unsigned smem_u32(const void* p) {
    return (unsigned)__cvta_generic_to_shared(p);
}
__device__ __forceinline__ void ldsm4(unsigned& r0, unsigned& r1,
                                      unsigned& r2, unsigned& r3, unsigned a) {
    asm volatile("ldmatrix.sync.aligned.m8n8.x4.shared.b16 {%0,%1,%2,%3}, [%4];"
                 : "=r"(r0), "=r"(r1), "=r"(r2), "=r"(r3) : "r"(a));
}
__device__ __forceinline__ void ldsm4t(unsigned& r0, unsigned& r1,
                                       unsigned& r2, unsigned& r3, unsigned a) {
    asm volatile("ldmatrix.sync.aligned.m8n8.x4.trans.shared.b16 {%0,%1,%2,%3}, [%4];"
                 : "=r"(r0), "=r"(r1), "=r"(r2), "=r"(r3) : "r"(a));
}
__device__ __forceinline__ void mma16816(float* d, const unsigned* a, const unsigned* b) {
    asm volatile("mma.sync.aligned.m16n8k16.row.col.f32.bf16.bf16.f32 "
                 "{%0,%1,%2,%3}, {%4,%5,%6,%7}, {%8,%9}, {%0,%1,%2,%3};"
                 : "+f"(d[0]), "+f"(d[1]), "+f"(d[2]), "+f"(d[3])
                 : "r"(a[0]), "r"(a[1]), "r"(a[2]), "r"(a[3]),
                   "r"(b[0]), "r"(b[1]));
}
__device__ __forceinline__ void split1(bf16* hp, bf16* lp, float v) {
    bf16 h = __float2bfloat16(v);
    *hp = h;
    *lp = __float2bfloat16(v - __bfloat162float(h));
}
__device__ __forceinline__ void split2(bf16* hp, bf16* lp, float v0, float v1) {
    __nv_bfloat162 h, l;
    h.x = __float2bfloat16(v0);
    h.y = __float2bfloat16(v1);
    l.x = __float2bfloat16(v0 - __bfloat162float(h.x));
    l.y = __float2bfloat16(v1 - __bfloat162float(h.y));
    *(__nv_bfloat162*)hp = h;
    *(__nv_bfloat162*)lp = l;
}

// ---------------- fp32 -> hi/lo bf16 split (elementwise) ----------------
__global__ void split_kernel(const float* __restrict__ src,
                             bf16* __restrict__ hi, bf16* __restrict__ lo, long n)
{
    long i = ((long)blockIdx.x * blockDim.x + threadIdx.x) * 4;
    if (i >= n) return;
    float4 v = *(const float4*)(src + i);
    split2(hi + i, lo + i, v.x, v.y);
    split2(hi + i + 2, lo + i + 2, v.z, v.w);
}

// =====================================================================
// Batched tensor-core GEMM on pre-split bf16 hi/lo operands.
// C[z] (M x N) = A[z] (M x K) * B[z] (K x N); 3-product split.
// Output: fp32 C, or hi/lo pair (Ch != nullptr).
// =====================================================================
__global__ __launch_bounds__(256)
void bgemm16_kernel(const bf16* __restrict__ Ah, const bf16* __restrict__ Al,
                    long Ao, long Ai,
                    const bf16* __restrict__ Bh, const bf16* __restrict__ Bl,
                    long Bo, long Bi,
                    float* __restrict__ C, bf16* __restrict__ Ch, bf16* __restrict__ Cl,
                    long Co, long Ci,
                    int zmod, int lda, int ldb, int ldc,
                    int K, int head_in, int head_off, int causal)
{
    __shared__ __align__(16) bf16 sAh[128 * ASTR];
    __shared__ __align__(16) bf16 sAl[128 * ASTR];
    __shared__ __align__(16) bf16 sBh[32 * BSTR];
    __shared__ __align__(16) bf16 sBl[32 * BSTR];

    const int z = blockIdx.z;
    const long zb = (long)(z / zmod), zi = (long)(z % zmod);
    const bf16* Ahb = Ah + zb * Ao + zi * Ai;
    const bf16* Alb = Al + zb * Ao + zi * Ai;
    const bf16* Bhb = Bh + zb * Bo + zi * Bi;
    const bf16* Blb = Bl + zb * Bo + zi * Bi;

    const int tid = threadIdx.x;
    const int wid = tid >> 5, lane = tid & 31;
    const int wm = (wid & 1) * 64;
    const int wn = (wid >> 1) * 32;
    const int row0 = blockIdx.y * 128;
    const int col0 = blockIdx.x * 128;
    const int Keff = causal ? min(K, (int)(blockIdx.y + 1) * 128) : K;

    float acc[4][4][4];
    #pragma unroll
    for (int i = 0; i < 4; i++)
        #pragma unroll
        for (int j = 0; j < 4; j++)
            #pragma unroll
            for (int r = 0; r < 4; r++) acc[i][j][r] = 0.f;

    for (int k0 = 0; k0 < Keff; k0 += 32) {
        // A tiles 128x32 (hi+lo), 8 bf16 per uint4
        #pragma unroll
        for (int m = 0; m < 2; m++) {
            const int f = tid * 2 + m;          // 0..511
            const int r = f >> 2;               // 0..127
            const int c = (f & 3) * 8;          // 0,8,16,24
            const long gi = (long)(row0 + r) * lda + k0 + c;
            *(uint4*)&sAh[r * ASTR + c] = *(const uint4*)(Ahb + gi);
            *(uint4*)&sAl[r * ASTR + c] = *(const uint4*)(Alb + gi);
        }
        // B tiles 32x128 (hi+lo)
        #pragma unroll
        for (int m = 0; m < 2; m++) {
            const int f = tid * 2 + m;          // 0..511
            const int r = f >> 4;               // 0..31
            const int c = (f & 15) * 8;         // 0..120
            const long gi = (long)(k0 + r) * ldb + col0 + c;
            *(uint4*)&sBh[r * BSTR + c] = *(const uint4*)(Bhb + gi);
            *(uint4*)&sBl[r * BSTR + c] = *(const uint4*)(Blb + gi);
        }
        __syncthreads();

        #pragma unroll
        for (int kk = 0; kk < 32; kk += 16) {
            unsigned ah[4][4], al[4][4], bh[4][2], bl[4][2];
            #pragma unroll
            for (int mi = 0; mi < 4; mi++) {
                const int off = (wm + mi * 16 + (lane & 15)) * ASTR + kk + (lane >> 4) * 8;
                ldsm4(ah[mi][0], ah[mi][1], ah[mi][2], ah[mi][3], smem_u32(&sAh[off]));
                ldsm4(al[mi][0], al[mi][1], al[mi][2], al[mi][3], smem_u32(&sAl[off]));
            }
            #pragma unroll
            for (int np = 0; np < 2; np++) {
                const int off = (kk + (lane & 15)) * BSTR + wn + np * 16 + (lane >> 4) * 8;
                ldsm4t(bh[np*2][0], bh[np*2][1], bh[np*2+1][0], bh[np*2+1][1],
                       smem_u32(&sBh[off]));
                ldsm4t(bl[np*2][0], bl[np*2][1], bl[np*2+1][0], bl[np*2+1][1],
                       smem_u32(&sBl[off]));
            }
            #pragma unroll
            for (int mi = 0; mi < 4; mi++)
                #pragma unroll
                for (int nj = 0; nj < 4; nj++) {
                    mma16816(acc[mi][nj], ah[mi], bh[nj]);
                    mma16816(acc[mi][nj], ah[mi], bl[nj]);
                    mma16816(acc[mi][nj], al[mi], bh[nj]);
                }
        }
        __syncthreads();
    }

    const int g = lane >> 2, t = lane & 3;
    #pragma unroll
    for (int mi = 0; mi < 4; mi++) {
        #pragma unroll
        for (int nj = 0; nj < 4; nj++) {
            const int c = col0 + wn + nj * 8 + t * 2;
            const int oc = (head_in > 0)
                ? (c / head_in) * DQK + head_off + (c % head_in) : c;
            #pragma unroll
            for (int rr = 0; rr < 2; rr++) {
                const int r = row0 + wm + mi * 16 + g + rr * 8;
                const long zo = zb * Co + zi * Ci + (long)r * ldc + oc;
                const float v0 = acc[mi][nj][rr * 2 + 0];
                const float v1 = acc[mi][nj][rr * 2 + 1];
                if (Ch) split2(Ch + zo, Cl + zo, v0, v1);
                else    *(float2*)(C + zo) = make_float2(v0, v1);
            }
        }
    }
}

// =====================================================================
// Tensor-core scores on pre-split q/k: S = Q Kt * SCALE, causal masked.
// q,k bf16 hi/lo layout (B,T,H,192), row stride 3072.
// B-operand = K row-major == Kt col-major -> NON-trans ldmatrix.
// =====================================================================
__global__ __launch_bounds__(256)
void scores16_kernel(const bf16* __restrict__ qh, const bf16* __restrict__ ql,
                     const bf16* __restrict__ kh, const bf16* __restrict__ kl,
                     float* __restrict__ sc)
{
    const int kt = blockIdx.x, qt = blockIdx.y, z = blockIdx.z;
    if (kt > qt) return;
    const int b = z >> 4, h = z & 15;
    const long base = (long)b * TT * HH * DQK + (long)h * DQK;
    const int q0 = qt * 128, k0 = kt * 128;
    const int RS = HH * DQK;   // 3072

    __shared__ __align__(16) bf16 sQh[128 * ASTR];
    __shared__ __align__(16) bf16 sQl[128 * ASTR];
    __shared__ __align__(16) bf16 sKh[128 * ASTR];
    __shared__ __align__(16) bf16 sKl[128 * ASTR];

    const int tid = threadIdx.x;
    const int wid = tid >> 5, lane = tid & 31;
    const int wm = (wid & 1) * 64;
    const int wn = (wid >> 1) * 32;

    float acc[4][4][4];
    #pragma unroll
    for (int i = 0; i < 4; i++)
        #pragma unroll
        for (int j = 0; j < 4; j++)
            #pragma unroll
            for (int r = 0; r < 4; r++) acc[i][j][r] = 0.f;

    for (int d0 = 0; d0 < DQK; d0 += 32) {
        #pragma unroll
        for (int m = 0; m < 2; m++) {
            const int f = tid * 2 + m;
            const int r = f >> 2;
            const int c = (f & 3) * 8;
            const long qi = base + (long)(q0 + r) * RS + d0 + c;
            const long ki = base + (long)(k0 + r) * RS + d0 + c;
            *(uint4*)&sQh[r * ASTR + c] = *(const uint4*)(qh + qi);
            *(uint4*)&sQl[r * ASTR + c] = *(const uint4*)(ql + qi);
            *(uint4*)&sKh[r * ASTR + c] = *(const uint4*)(kh + ki);
            *(uint4*)&sKl[r * ASTR + c] = *(const uint4*)(kl + ki);
        }
        __syncthreads();

        #pragma unroll
        for (int kk = 0; kk < 32; kk += 16) {
            unsigned ah[4][4], al[4][4], bh[4][2], bl[4][2];
            #pragma unroll
            for (int mi = 0; mi < 4; mi++) {
                const int off = (wm + mi * 16 + (lane & 15)) * ASTR + kk + (lane >> 4) * 8;
                ldsm4(ah[mi][0], ah[mi][1], ah[mi][2], ah[mi][3], smem_u32(&sQh[off]));
                ldsm4(al[mi][0], al[mi][1], al[mi][2], al[mi][3], smem_u32(&sQl[off]));
            }
            #pragma unroll
            for (int np = 0; np < 2; np++) {
                const int off = (wn + np * 16 + (lane & 15)) * ASTR + kk + (lane >> 4) * 8;
                unsigned r0, r1, r2, r3;
                ldsm4(r0, r1, r2, r3, smem_u32(&sKh[off]));
                bh[np*2][0] = r0; bh[np*2][1] = r2;
                bh[np*2+1][0] = r1; bh[np*2+1][1] = r3;
                ldsm4(r0, r1, r2, r3, smem_u32(&sKl[off]));
                bl[np*2][0] = r0; bl[np*2][1] = r2;
                bl[np*2+1][0] = r1; bl[np*2+1][1] = r3;
            }
            #pragma unroll
            for (int mi = 0; mi < 4; mi++)
                #pragma unroll
                for (int nj = 0; nj < 4; nj++) {
                    mma16816(acc[mi][nj], ah[mi], bh[nj]);
                    mma16816(acc[mi][nj], ah[mi], bl[nj]);
                    mma16816(acc[mi][nj], al[mi], bh[nj]);
                }
        }
        __syncthreads();
    }

    float* out = sc + (long)z * TT * TT;
    const int g = lane >> 2, t = lane & 3;
    #pragma unroll
    for (int mi = 0; mi < 4; mi++) {
        #pragma unroll
        for (int nj = 0; nj < 4; nj++) {
            #pragma unroll
            for (int rr = 0; rr < 2; rr++) {
                const int qi = q0 + wm + mi * 16 + g + rr * 8;
                const int kj = k0 + wn + nj * 8 + t * 2;
                float v0 = acc[mi][nj][rr * 2 + 0] * SCALE;
                float v1 = acc[mi][nj][rr * 2 + 1] * SCALE;
                if (qt == kt) {
                    if (kj + 0 > qi) v0 = -INFINITY;
                    if (kj + 1 > qi) v1 = -INFINITY;
                }
                *(float2*)(out + (long)qi * TT + kj) = make_float2(v0, v1);
            }
        }
    }
}

// ---------------- 64x64 fp32 SGEMM (W_KR, N=64) ----------------
#define BM 64
#define BN 64
#define BKT 16

__global__ __launch_bounds__(256)
void sgemm_kernel(const float* __restrict__ A,
                  const float* __restrict__ Bp,
                  float* __restrict__ C,
                  int lda, int ldb, int ldc, int K)
{
    const int row0 = blockIdx.y * BM;
    const int col0 = blockIdx.x * BN;

    __shared__ float As[BKT][BM];
    __shared__ float Bs[BKT][BN];

    const int tid = threadIdx.x;
    const int tx = tid & 15, ty = tid >> 4;
    const int arow = tid >> 2,  acol = (tid & 3) * 4;
    const int brow = tid >> 4,  bcol = (tid & 15) * 4;

    float acc[4][4] = {};

    for (int k0 = 0; k0 < K; k0 += BKT) {
        float4 av = *(const float4*)(A + (long)(row0 + arow) * lda + k0 + acol);
        As[acol + 0][arow] = av.x;
        As[acol + 1][arow] = av.y;
        As[acol + 2][arow] = av.z;
        As[acol + 3][arow] = av.w;
        float4 bv = *(const float4*)(Bp + (long)(k0 + brow) * ldb + col0 + bcol);
        *(float4*)&Bs[brow][bcol] = bv;
        __syncthreads();
        #pragma unroll
        for (int kk = 0; kk < BKT; kk++) {
            float4 af = *(const float4*)&As[kk][ty * 4];
            float4 bf = *(const float4*)&Bs[kk][tx * 4];
            float a0[4] = {af.x, af.y, af.z, af.w};
            float b0[4] = {bf.x, bf.y, bf.z, bf.w};
            #pragma unroll
            for (int i = 0; i < 4; i++)
                #pragma unroll
                for (int j = 0; j < 4; j++)
                    acc[i][j] = fmaf(a0[i], b0[j], acc[i][j]);
        }
        __syncthreads();
    }

    #pragma unroll
    for (int i = 0; i < 4; i++) {
        const int r = row0 + ty * 4 + i;
        #pragma unroll
        for (int j = 0; j < 4; j++)
            C[(long)r * ldc + col0 + tx * 4 + j] = acc[i][j];
    }
}

// ---------------- RMSNorm: fp32 in -> hi/lo bf16 out ----------------
__global__ __launch_bounds__(256)
void rmsnorm16_kernel(const float* __restrict__ x, const float* __restrict__ w,
                      bf16* __restrict__ hi, bf16* __restrict__ lo, int len)
{
    const float* p = x + (long)blockIdx.x * len;
    bf16* ph = hi + (long)blockIdx.x * len;
    bf16* pl = lo + (long)blockIdx.x * len;
    __shared__ float red[256];
    const int tid = threadIdx.x;
    float s = 0.f;
    for (int i = tid; i < len; i += 256) { float v = p[i]; s += v * v; }
    red[tid] = s; __syncthreads();
    for (int d = 128; d > 0; d >>= 1) { if (tid < d) red[tid] += red[tid + d]; __syncthreads(); }
    const float inv = rsqrtf(red[0] / (float)len + EPS);
    for (int i = tid; i < len; i += 256)
        split1(ph + i, pl + i, p[i] * inv * w[i]);
}

// ---------------- RoPE q: fp32 staging -> hi/lo into qh/ql ----------------
__global__ void rope_q16_kernel(const float* __restrict__ qf,
                                bf16* __restrict__ qh, bf16* __restrict__ ql)
{
    long idx = (long)blockIdx.x * blockDim.x + threadIdx.x;   // B*T*H*32
    if (idx >= (long)NTOK * HH * 32) return;
    const int i = idx & 31;
    const int h = (idx >> 5) & 15;
    const long tok = idx >> 9;
    const int t = (int)(tok & (TT - 1));
    const float inv = powf(500000.0f, -(float)i / 32.0f);
    float c, s;
    sincosf((float)t * inv, &s, &c);
    const long off = tok * (HH * DQK) + (long)h * DQK + DH;
    const float a = qf[off + i], b = qf[off + i + 32];
    split1(qh + off + i,      ql + off + i,      a * c - b * s);
    split1(qh + off + i + 32, ql + off + i + 32, b * c + a * s);
}

// ---------------- RoPE k_R + broadcast into kh/kl for all heads ----------------
__global__ void rope_k16_kernel(const float* __restrict__ kR,
                                bf16* __restrict__ kh, bf16* __restrict__ kl)
{
    long idx = (long)blockIdx.x * blockDim.x + threadIdx.x;   // B*T*32
    if (idx >= (long)NTOK * 32) return;
    const int i = idx & 31;
    const long tok = idx >> 5;
    const int t = (int)(tok & (TT - 1));
    const float inv = powf(500000.0f, -(float)i / 32.0f);
    float c, s;
    sincosf((float)t * inv, &s, &c);
    const float a = kR[tok * DR + i], b = kR[tok * DR + i + 32];
    const float r0 = a * c - b * s;
    const float r1 = b * c + a * s;
    bf16 r0h = __float2bfloat16(r0);
    bf16 r0l = __float2bfloat16(r0 - __bfloat162float(r0h));
    bf16 r1h = __float2bfloat16(r1);
    bf16 r1l = __float2bfloat16(r1 - __bfloat162float(r1h));
    const long base = tok * (HH * DQK) + DH;
    #pragma unroll
    for (int h = 0; h < HH; h++) {
        kh[base + (long)h * DQK + i]      = r0h;
        kl[base + (long)h * DQK + i]      = r0l;
        kh[base + (long)h * DQK + i + 32] = r1h;
        kl[base + (long)h * DQK + i + 32] = r1l;
    }
}

// ---------------- row softmax: fp32 scores -> hi/lo bf16 probs ----------------
__global__ __launch_bounds__(256)
void softmax16_kernel(const float* __restrict__ sc,
                      bf16* __restrict__ ph, bf16* __restrict__ pl)
{
    const int qpos = blockIdx.x, z = blockIdx.y;
    const float* row = sc + ((long)z * TT + qpos) * TT;
    bf16* rh = ph + ((long)z * TT + qpos) * TT;
    bf16* rl = pl + ((long)z * TT + qpos) * TT;
    const int kend = ((qpos >> 7) + 1) << 7;      // 128-tile padded
    __shared__ float buf[2048];
    __shared__ float red[256];
    const int tid = threadIdx.x;

    float m = -INFINITY;
    for (int i = tid; i < kend; i += 256) m = fmaxf(m, row[i]);
    red[tid] = m; __syncthreads();
    for (int d = 128; d > 0; d >>= 1) { if (tid < d) red[tid] = fmaxf(red[tid], red[tid + d]); __syncthreads(); }
    m = red[0]; __syncthreads();

    float s = 0.f;
    for (int i = tid; i < kend; i += 256) { float e = expf(row[i] - m); buf[i] = e; s += e; }
    red[tid] = s; __syncthreads();
    for (int d = 128; d > 0; d >>= 1) { if (tid < d) red[tid] += red[tid + d]; __syncthreads(); }
    const float inv = 1.0f / red[0];
    for (int i = tid; i < kend; i += 256)
        split1(rh + i, rl + i, buf[i] * inv);
}

// ---------------- launch ----------------
extern "C" void kernel_launch(void* const* d_in, const int* in_sizes, int n_in,
                              void* d_out, int out_size)
{
    const float* x     = (const float*)d_in[0];
    const float* W_DQ  = (const float*)d_in[1];
    const float* W_UQ  = (const float*)d_in[2];
    const float* W_QR  = (const float*)d_in[3];
    const float* W_DKV = (const float*)d_in[4];
    const float* W_UK  = (const float*)d_in[5];
    const float* W_UV  = (const float*)d_in[6];
    const float* W_KR  = (const float*)d_in[7];
    const float* W_O   = (const float*)d_in[8];
    const float* qnw   = (const float*)d_in[9];
    const float* kvnw  = (const float*)d_in[10];
    float* out = (float*)d_out;

    float *cQ, *cKV, *qf, *kR, *sc;
    bf16 *xh, *xl, *wh, *wl, *cQh, *cQl, *cKVh, *cKVl;
    bf16 *qh, *ql, *kh, *kl, *vh, *vl, *ph, *pl, *aoh, *aol;
    cudaGetSymbolAddress((void**)&cQ,   g_cQ);
    cudaGetSymbolAddress((void**)&cKV,  g_cKV);
    cudaGetSymbolAddress((void**)&qf,   g_qf);
    cudaGetSymbolAddress((void**)&kR,   g_kR);
    cudaGetSymbolAddress((void**)&sc,   g_sc);
    cudaGetSymbolAddress((void**)&xh,   g_xh);
    cudaGetSymbolAddress((void**)&xl,   g_xl);
    cudaGetSymbolAddress((void**)&wh,   g_wh);
    cudaGetSymbolAddress((void**)&wl,   g_wl);
    cudaGetSymbolAddress((void**)&cQh,  g_cQh);
    cudaGetSymbolAddress((void**)&cQl,  g_cQl);
    cudaGetSymbolAddress((void**)&cKVh, g_cKVh);
    cudaGetSymbolAddress((void**)&cKVl, g_cKVl);
    cudaGetSymbolAddress((void**)&qh,   g_qh);
    cudaGetSymbolAddress((void**)&ql,   g_ql);
    cudaGetSymbolAddress((void**)&kh,   g_kh);
    cudaGetSymbolAddress((void**)&kl,   g_kl);
    cudaGetSymbolAddress((void**)&vh,   g_vh);
    cudaGetSymbolAddress((void**)&vl,   g_vl);
    cudaGetSymbolAddress((void**)&ph,   g_ph);
    cudaGetSymbolAddress((void**)&pl,   g_pl);
    cudaGetSymbolAddress((void**)&aoh,  g_aoh);
    cudaGetSymbolAddress((void**)&aol,  g_aol);

    const dim3 blk(256);
    #define SPLIT(src, h, l, n) \
        split_kernel<<<(unsigned)(((n)/4 + 255)/256), blk>>>(src, h, l, (long)(n))

    // 0) pre-split inputs and weights
    SPLIT(x,     xh,           xl,           (long)NTOK*DD);
    SPLIT(W_DQ,  wh + OFF_DQ,  wl + OFF_DQ,  (long)DD*DQ);
    SPLIT(W_UQ,  wh + OFF_UQ,  wl + OFF_UQ,  (long)DQ*HH*DH);
    SPLIT(W_QR,  wh + OFF_QR,  wl + OFF_QR,  (long)DQ*HH*DR);
    SPLIT(W_DKV, wh + OFF_DKV, wl + OFF_DKV, (long)DD*DKV);
    SPLIT(W_UK,  wh + OFF_UK,  wl + OFF_UK,  (long)DKV*HH*DH);
    SPLIT(W_UV,  wh + OFF_UV,  wl + OFF_UV,  (long)DKV*HH*DH);
    SPLIT(W_O,   wh + OFF_O,   wl + OFF_O,   (long)HH*DH*DD);

    // 1) c_Q = x @ W_DQ ; RMSNorm -> hi/lo
    bgemm16_kernel<<<dim3(DQ/128, NTOK/128, 1), blk>>>(
        xh, xl, 0, 0, wh + OFF_DQ, wl + OFF_DQ, 0, 0,
        cQ, nullptr, nullptr, 0, 0, 1, DD, DQ, DQ, DD, 0, 0, 0);
    rmsnorm16_kernel<<<NTOK, blk>>>(cQ, qnw, cQh, cQl, DQ);

    // 2) c_KV = x @ W_DKV ; RMSNorm -> hi/lo
    bgemm16_kernel<<<dim3(DKV/128, NTOK/128, 1), blk>>>(
        xh, xl, 0, 0, wh + OFF_DKV, wl + OFF_DKV, 0, 0,
        cKV, nullptr, nullptr, 0, 0, 1, DD, DKV, DKV, DD, 0, 0, 0);
    rmsnorm16_kernel<<<NTOK, blk>>>(cKV, kvnw, cKVh, cKVl, DKV);

    // 3) q content -> qh/ql (remap); q rope -> fp32 staging
    bgemm16_kernel<<<dim3((HH*DH)/128, NTOK/128, 1), blk>>>(
        cQh, cQl, 0, 0, wh + OFF_UQ, wl + OFF_UQ, 0, 0,
        nullptr, qh, ql, 0, 0, 1, DQ, HH*DH, HH*DQK, DQ, DH, 0, 0);
    bgemm16_kernel<<<dim3((HH*DR)/128, NTOK/128, 1), blk>>>(
        cQh, cQl, 0, 0, wh + OFF_QR, wl + OFF_QR, 0, 0,
        qf, nullptr, nullptr, 0, 0, 1, DQ, HH*DR, HH*DQK, DQ, DR, DH, 0);

    // 4) k content -> kh/kl (remap); v -> vh/vl
    bgemm16_kernel<<<dim3((HH*DH)/128, NTOK/128, 1), blk>>>(
        cKVh, cKVl, 0, 0, wh + OFF_UK, wl + OFF_UK, 0, 0,
        nullptr, kh, kl, 0, 0, 1, DKV, HH*DH, HH*DQK, DKV, DH, 0, 0);
    bgemm16_kernel<<<dim3((HH*DH)/128, NTOK/128, 1), blk>>>(
        cKVh, cKVl, 0, 0, wh + OFF_UV, wl + OFF_UV, 0, 0,
        nullptr, vh, vl, 0, 0, 1, DKV, HH*DH, HH*DH, DKV, 0, 0, 0);

    // 5) k_R = x @ W_KR (fp32)
    sgemm_kernel<<<dim3(DR/64, NTOK/64), blk>>>(x, W_KR, kR, DD, DR, DR, DD);

    // 6) RoPE -> hi/lo
    rope_q16_kernel<<<(unsigned)(((long)NTOK*HH*32 + 255)/256), blk>>>(qf, qh, ql);
    rope_k16_kernel<<<(unsigned)(((long)NTOK*32 + 255)/256), blk>>>(kR, kh, kl);

    // 7) attention: scores -> softmax -> PV
    scores16_kernel<<<dim3(TT/128, TT/128, BHZ), blk>>>(qh, ql, kh, kl, sc);
    softmax16_kernel<<<dim3(TT, BHZ), blk>>>(sc, ph, pl);

    bgemm16_kernel<<<dim3(1, TT/128, BHZ), blk>>>(
        ph, pl, (long)HH*TT*TT, (long)TT*TT,
        vh, vl, (long)TT*HH*DH, (long)DH,
        nullptr, aoh, aol, (long)TT*HH*DH, (long)DH,
        HH, TT, HH*DH, HH*DH, TT, 0, 0, 1);

    // 8) final: out = ao @ W_O (fp32 out)
    bgemm16_kernel<<<dim3(DD/128, NTOK/128, 1), blk>>>(
        aoh, aol, 0, 0, wh + OFF_O, wl + OFF_O, 0, 0,
        out, nullptr, nullptr, 0, 0, 1, HH*DH, DD, DD, HH*DH, 0, 0, 0);
}

// round 16
// speedup vs baseline: 1.0531x; 1.0531x over previous
#include <cuda_runtime.h>
#include <cuda_bf16.h>
#include <cstdint>
#include <math.h>

// ---------------- problem constants ----------------
#define BATCH 2
#define TT    2048
#define DD    2048
#define HH    16
#define DH    128
#define DKV   512
#define DQ    1024
#define DR    64
#define DQK   192            // DH + DR
#define NTOK  (BATCH*TT)     // 4096
#define BHZ   (BATCH*HH)     // 32
#define EPS   1e-6f
#define SCALE 0.072168783648703220563f   // 1/sqrt(192)

typedef __nv_bfloat16 bf16;

// ---------------- weight arena offsets (elements) ----------------
#define OFF_DQ  0L
#define OFF_UQ  2097152L
#define OFF_QR  4194304L
#define OFF_DKV 5242880L
#define OFF_UK  6291456L
#define OFF_UV  7340032L
#define OFF_O   8388608L
#define W_TOTAL 12582912L

// ---------------- scratch (device globals; allocation-free) ----------------
__device__ __align__(16) float g_cQ  [(size_t)NTOK * DQ];
__device__ __align__(16) float g_cKV [(size_t)NTOK * DKV];
__device__ __align__(16) float g_qf  [(size_t)NTOK * HH * DQK];
__device__ __align__(16) float g_kR  [(size_t)NTOK * DR];

__device__ __align__(16) bf16 g_xh  [(size_t)NTOK * DD];
__device__ __align__(16) bf16 g_xl  [(size_t)NTOK * DD];
__device__ __align__(16) bf16 g_wh  [W_TOTAL];
__device__ __align__(16) bf16 g_wl  [W_TOTAL];
__device__ __align__(16) bf16 g_cQh [(size_t)NTOK * DQ];
__device__ __align__(16) bf16 g_cQl [(size_t)NTOK * DQ];
__device__ __align__(16) bf16 g_cKVh[(size_t)NTOK * DKV];
__device__ __align__(16) bf16 g_cKVl[(size_t)NTOK * DKV];
__device__ __align__(16) bf16 g_qh  [(size_t)NTOK * HH * DQK];
__device__ __align__(16) bf16 g_ql  [(size_t)NTOK * HH * DQK];
__device__ __align__(16) bf16 g_kh  [(size_t)NTOK * HH * DQK];
__device__ __align__(16) bf16 g_kl  [(size_t)NTOK * HH * DQK];
__device__ __align__(16) bf16 g_vh  [(size_t)NTOK * HH * DH];
__device__ __align__(16) bf16 g_vl  [(size_t)NTOK * HH * DH];
__device__ __align__(16) bf16 g_aoh [(size_t)NTOK * HH * DH];
__device__ __align__(16) bf16 g_aol [(size_t)NTOK * HH * DH];

// =====================================================================
// helpers
// =====================================================================
#define ASTR 40
#define BSTR 136

__device__ __forceinline__ unsigned smem_u32(const void* p) {
    return (unsigned)__cvta_generic_to_shared(p);
}
__device__ __forceinline__ void ldsm4(unsigned& r0, unsigned& r1,
                                      unsigned& r2, unsigned& r3, unsigned a) {
    asm volatile("ldmatrix.sync.aligned.m8n8.x4.shared.b16 {%0,%1,%2,%3}, [%4];"
                 : "=r"(r0), "=r"(r1), "=r"(r2), "=r"(r3) : "r"(a));
}
__device__ __forceinline__ void ldsm4t(unsigned& r0, unsigned& r1,
                                       unsigned& r2, unsigned& r3, unsigned a) {
    asm volatile("ldmatrix.sync.aligned.m8n8.x4.trans.shared.b16 {%0,%1,%2,%3}, [%4];"
                 : "=r"(r0), "=r"(r1), "=r"(r2), "=r"(r3) : "r"(a));
}
__device__ __forceinline__ void mma16816(float* d, const unsigned* a, const unsigned* b) {
    asm volatile("mma.sync.aligned.m16n8k16.row.col.f32.bf16.bf16.f32 "
                 "{%0,%1,%2,%3}, {%4,%5,%6,%7}, {%8,%9}, {%0,%1,%2,%3};"
                 : "+f"(d[0]), "+f"(d[1]), "+f"(d[2]), "+f"(d[3])
                 : "r"(a[0]), "r"(a[1]), "r"(a[2]), "r"(a[3]),
                   "r"(b[0]), "r"(b[1]));
}
__device__ __forceinline__ void split1(bf16* hp, bf16* lp, float v) {
    bf16 h = __float2bfloat16(v);
    *hp = h;
    *lp = __float2bfloat16(v - __bfloat162float(h));
}
__device__ __forceinline__ void split2(bf16* hp, bf16* lp, float v0, float v1) {
    __nv_bfloat162 h, l;
    h.x = __float2bfloat16(v0);
    h.y = __float2bfloat16(v1);
    l.x = __float2bfloat16(v0 - __bfloat162float(h.x));
    l.y = __float2bfloat16(v1 - __bfloat162float(h.y));
    *(__nv_bfloat162*)hp = h;
    *(__nv_bfloat162*)lp = l;
}

// ---------------- fp32 -> hi/lo bf16 split (elementwise) ----------------
__global__ void split_kernel(const float* __restrict__ src,
                             bf16* __restrict__ hi, bf16* __restrict__ lo, long n)
{
    long i = ((long)blockIdx.x * blockDim.x + threadIdx.x) * 4;
    if (i >= n) return;
    float4 v = *(const float4*)(src + i);
    split2(hi + i, lo + i, v.x, v.y);
    split2(hi + i + 2, lo + i + 2, v.z, v.w);
}

// =====================================================================
// Batched tensor-core GEMM on pre-split bf16 hi/lo operands (projections)
// =====================================================================
__global__ __launch_bounds__(256)
void bgemm16_kernel(const bf16* __restrict__ Ah, const bf16* __restrict__ Al,
                    long Ao, long Ai,
                    const bf16* __restrict__ Bh, const bf16* __restrict__ Bl,
                    long Bo, long Bi,
                    float* __restrict__ C, bf16* __restrict__ Ch, bf16* __restrict__ Cl,
                    long Co, long Ci,
                    int zmod, int lda, int ldb, int ldc,
                    int K, int head_in, int head_off, int causal)
{
    __shared__ __align__(16) bf16 sAh[128 * ASTR];
    __shared__ __align__(16) bf16 sAl[128 * ASTR];
    __shared__ __align__(16) bf16 sBh[32 * BSTR];
    __shared__ __align__(16) bf16 sBl[32 * BSTR];

    const int z = blockIdx.z;
    const long zb = (long)(z / zmod), zi = (long)(z % zmod);
    const bf16* Ahb = Ah + zb * Ao + zi * Ai;
    const bf16* Alb = Al + zb * Ao + zi * Ai;
    const bf16* Bhb = Bh + zb * Bo + zi * Bi;
    const bf16* Blb = Bl + zb * Bo + zi * Bi;

    const int tid = threadIdx.x;
    const int wid = tid >> 5, lane = tid & 31;
    const int wm = (wid & 1) * 64;
    const int wn = (wid >> 1) * 32;
    const int row0 = blockIdx.y * 128;
    const int col0 = blockIdx.x * 128;
    const int Keff = causal ? min(K, (int)(blockIdx.y + 1) * 128) : K;

    float acc[4][4][4];
    #pragma unroll
    for (int i = 0; i < 4; i++)
        #pragma unroll
        for (int j = 0; j < 4; j++)
            #pragma unroll
            for (int r = 0; r < 4; r++) acc[i][j][r] = 0.f;

    for (int k0 = 0; k0 < Keff; k0 += 32) {
        #pragma unroll
        for (int m = 0; m < 2; m++) {
            const int f = tid * 2 + m;
            const int r = f >> 2;
            const int c = (f & 3) * 8;
            const long gi = (long)(row0 + r) * lda + k0 + c;
            *(uint4*)&sAh[r * ASTR + c] = *(const uint4*)(Ahb + gi);
            *(uint4*)&sAl[r * ASTR + c] = *(const uint4*)(Alb + gi);
        }
        #pragma unroll
        for (int m = 0; m < 2; m++) {
            const int f = tid * 2 + m;
            const int r = f >> 4;
            const int c = (f & 15) * 8;
            const long gi = (long)(k0 + r) * ldb + col0 + c;
            *(uint4*)&sBh[r * BSTR + c] = *(const uint4*)(Bhb + gi);
            *(uint4*)&sBl[r * BSTR + c] = *(const uint4*)(Blb + gi);
        }
        __syncthreads();

        #pragma unroll
        for (int kk = 0; kk < 32; kk += 16) {
            unsigned ah[4][4], al[4][4], bh[4][2], bl[4][2];
            #pragma unroll
            for (int mi = 0; mi < 4; mi++) {
                const int off = (wm + mi * 16 + (lane & 15)) * ASTR + kk + (lane >> 4) * 8;
                ldsm4(ah[mi][0], ah[mi][1], ah[mi][2], ah[mi][3], smem_u32(&sAh[off]));
                ldsm4(al[mi][0], al[mi][1], al[mi][2], al[mi][3], smem_u32(&sAl[off]));
            }
            #pragma unroll
            for (int np = 0; np < 2; np++) {
                const int off = (kk + (lane & 15)) * BSTR + wn + np * 16 + (lane >> 4) * 8;
                ldsm4t(bh[np*2][0], bh[np*2][1], bh[np*2+1][0], bh[np*2+1][1],
                       smem_u32(&sBh[off]));
                ldsm4t(bl[np*2][0], bl[np*2][1], bl[np*2+1][0], bl[np*2+1][1],
                       smem_u32(&sBl[off]));
            }
            #pragma unroll
            for (int mi = 0; mi < 4; mi++)
                #pragma unroll
                for (int nj = 0; nj < 4; nj++) {
                    mma16816(acc[mi][nj], ah[mi], bh[nj]);
                    mma16816(acc[mi][nj], ah[mi], bl[nj]);
                    mma16816(acc[mi][nj], al[mi], bh[nj]);
                }
        }
        __syncthreads();
    }

    const int g = lane >> 2, t = lane & 3;
    #pragma unroll
    for (int mi = 0; mi < 4; mi++) {
        #pragma unroll
        for (int nj = 0; nj < 4; nj++) {
            const int c = col0 + wn + nj * 8 + t * 2;
            const int oc = (head_in > 0)
                ? (c / head_in) * DQK + head_off + (c % head_in) : c;
            #pragma unroll
            for (int rr = 0; rr < 2; rr++) {
                const int r = row0 + wm + mi * 16 + g + rr * 8;
                const long zo = zb * Co + zi * Ci + (long)r * ldc + oc;
                const float v0 = acc[mi][nj][rr * 2 + 0];
                const float v1 = acc[mi][nj][rr * 2 + 1];
                if (Ch) split2(Ch + zo, Cl + zo, v0, v1);
                else    *(float2*)(C + zo) = make_float2(v0, v1);
            }
        }
    }
}

// =====================================================================
// Fused flash attention: S = QK^T*SCALE (causal) -> online softmax -> O = P V
// One CTA per (z, q-tile of 128). 8 warps; warp w owns q-rows w*16..w*16+15.
// K-tiles of 64. Inner loops load-then-consume per 16-col fragment to keep
// register pressure low (no batched fragment arrays).
// =====================================================================
#define QSTR 200
#define KSTR 200
#define VSTR 136
#define PSTR 72
#define FLASH_SMEM ((2*128*QSTR + 2*64*KSTR + 2*64*VSTR + 2*128*PSTR) * 2)

__global__ __launch_bounds__(256)
void flash_kernel(const bf16* __restrict__ qh, const bf16* __restrict__ ql,
                  const bf16* __restrict__ kh, const bf16* __restrict__ kl,
                  const bf16* __restrict__ vh, const bf16* __restrict__ vl,
                  bf16* __restrict__ aoh, bf16* __restrict__ aol)
{
    extern __shared__ __align__(16) bf16 smem[];
    bf16* sQh = smem;
    bf16* sQl = sQh + 128 * QSTR;
    bf16* sKh = sQl + 128 * QSTR;
    bf16* sKl = sKh + 64 * KSTR;
    bf16* sVh = sKl + 64 * KSTR;
    bf16* sVl = sVh + 64 * VSTR;
    bf16* sPh = sVl + 64 * VSTR;
    bf16* sPl = sPh + 128 * PSTR;

    const int qt = (int)gridDim.y - 1 - (int)blockIdx.y;   // big tiles first
    const int z  = blockIdx.x;
    const int b = z >> 4, h = z & 15;
    const int q0 = qt * 128;
    const long qkbase = (long)b * TT * (HH * DQK) + (long)h * DQK;
    const long vbase  = (long)b * TT * (HH * DH) + (long)h * DH;

    const int tid = threadIdx.x;
    const int wid = tid >> 5, lane = tid & 31;
    const int g = lane >> 2, t = lane & 3;
    const int wq = wid * 16;

    // load Q tile (128 x 192, hi+lo)
    for (int i = tid; i < 3072; i += 256) {
        const int r = i / 24;
        const int c = (i % 24) * 8;
        const long gi = qkbase + (long)(q0 + r) * (HH * DQK) + c;
        *(uint4*)&sQh[r * QSTR + c] = *(const uint4*)(qh + gi);
        *(uint4*)&sQl[r * QSTR + c] = *(const uint4*)(ql + gi);
    }

    float m_r[2] = {-1e30f, -1e30f};
    float l_r[2] = {0.f, 0.f};
    float acc_o[16][4];
    #pragma unroll
    for (int i = 0; i < 16; i++)
        #pragma unroll
        for (int r = 0; r < 4; r++) acc_o[i][r] = 0.f;

    const int qi0 = q0 + wq + g;       // thread's two rows
    const int qi1 = qi0 + 8;
    const int nkt = 2 * qt + 2;

    for (int kt = 0; kt < nkt; kt++) {
        const int k0 = kt * 64;
        __syncthreads();               // protect prior K/V use (and Q load at kt=0)
        // load K tile (64 x 192)
        for (int i = tid; i < 1536; i += 256) {
            const int r = i / 24;
            const int c = (i % 24) * 8;
            const long gi = qkbase + (long)(k0 + r) * (HH * DQK) + c;
            *(uint4*)&sKh[r * KSTR + c] = *(const uint4*)(kh + gi);
            *(uint4*)&sKl[r * KSTR + c] = *(const uint4*)(kl + gi);
        }
        // load V tile (64 x 128)
        for (int i = tid; i < 1024; i += 256) {
            const int r = i / 16;
            const int c = (i % 16) * 8;
            const long gi = vbase + (long)(k0 + r) * (HH * DH) + c;
            *(uint4*)&sVh[r * VSTR + c] = *(const uint4*)(vh + gi);
            *(uint4*)&sVl[r * VSTR + c] = *(const uint4*)(vl + gi);
        }
        __syncthreads();

        // ---- S = Q K^T (warp rows wq..wq+15, cols 0..63) ----
        float s[8][4];
        #pragma unroll
        for (int i = 0; i < 8; i++)
            #pragma unroll
            for (int r = 0; r < 4; r++) s[i][r] = 0.f;

        #pragma unroll
        for (int d0 = 0; d0 < DQK; d0 += 16) {
            unsigned ah[4], al[4];
            {
                const int off = (wq + (lane & 15)) * QSTR + d0 + (lane >> 4) * 8;
                ldsm4(ah[0], ah[1], ah[2], ah[3], smem_u32(&sQh[off]));
                ldsm4(al[0], al[1], al[2], al[3], smem_u32(&sQl[off]));
            }
            #pragma unroll
            for (int np = 0; np < 4; np++) {
                const int off = (np * 16 + (lane & 15)) * KSTR + d0 + (lane >> 4) * 8;
                unsigned r0, r1, r2, r3;
                unsigned b0[2], b1[2];
                ldsm4(r0, r1, r2, r3, smem_u32(&sKh[off]));
                b0[0] = r0; b0[1] = r2;
                b1[0] = r1; b1[1] = r3;
                mma16816(s[np*2],   ah, b0);
                mma16816(s[np*2],   al, b0);
                mma16816(s[np*2+1], ah, b1);
                mma16816(s[np*2+1], al, b1);
                ldsm4(r0, r1, r2, r3, smem_u32(&sKl[off]));
                b0[0] = r0; b0[1] = r2;
                b1[0] = r1; b1[1] = r3;
                mma16816(s[np*2],   ah, b0);
                mma16816(s[np*2+1], ah, b1);
            }
        }

        // ---- scale + causal mask + tile row-max ----
        const bool diag = (k0 + 63 > q0 + wq);
        float mt0 = -1e30f, mt1 = -1e30f;
        #pragma unroll
        for (int nf = 0; nf < 8; nf++) {
            #pragma unroll
            for (int e = 0; e < 2; e++) {
                const int kj = k0 + nf * 8 + t * 2 + e;
                float v0 = s[nf][e]     * SCALE;
                float v1 = s[nf][2 + e] * SCALE;
                if (diag) {
                    if (kj > qi0) v0 = -1e30f;
                    if (kj > qi1) v1 = -1e30f;
                }
                s[nf][e] = v0; s[nf][2 + e] = v1;
                mt0 = fmaxf(mt0, v0); mt1 = fmaxf(mt1, v1);
            }
        }
        mt0 = fmaxf(mt0, __shfl_xor_sync(0xffffffffu, mt0, 1));
        mt0 = fmaxf(mt0, __shfl_xor_sync(0xffffffffu, mt0, 2));
        mt1 = fmaxf(mt1, __shfl_xor_sync(0xffffffffu, mt1, 1));
        mt1 = fmaxf(mt1, __shfl_xor_sync(0xffffffffu, mt1, 2));

        const float mn0 = fmaxf(m_r[0], mt0);
        const float mn1 = fmaxf(m_r[1], mt1);
        const float a0 = __expf(m_r[0] - mn0);
        const float a1 = __expf(m_r[1] - mn1);
        m_r[0] = mn0; m_r[1] = mn1;
        l_r[0] *= a0; l_r[1] *= a1;
        #pragma unroll
        for (int nf = 0; nf < 16; nf++) {
            acc_o[nf][0] *= a0; acc_o[nf][1] *= a0;
            acc_o[nf][2] *= a1; acc_o[nf][3] *= a1;
        }

        // ---- P = exp(S - m), write hi/lo to smem ----
        #pragma unroll
        for (int nf = 0; nf < 8; nf++) {
            const float p00 = __expf(s[nf][0] - mn0);
            const float p01 = __expf(s[nf][1] - mn0);
            const float p10 = __expf(s[nf][2] - mn1);
            const float p11 = __expf(s[nf][3] - mn1);
            l_r[0] += p00 + p01;
            l_r[1] += p10 + p11;
            const int cb = nf * 8 + t * 2;
            split2(&sPh[(wq + g) * PSTR + cb],     &sPl[(wq + g) * PSTR + cb],     p00, p01);
            split2(&sPh[(wq + g + 8) * PSTR + cb], &sPl[(wq + g + 8) * PSTR + cb], p10, p11);
        }
        __syncwarp();

        // ---- O += P (16x64) * V (64x128) ----
        #pragma unroll
        for (int kk = 0; kk < 64; kk += 16) {
            unsigned ah[4], al[4];
            {
                const int off = (wq + (lane & 15)) * PSTR + kk + (lane >> 4) * 8;
                ldsm4(ah[0], ah[1], ah[2], ah[3], smem_u32(&sPh[off]));
                ldsm4(al[0], al[1], al[2], al[3], smem_u32(&sPl[off]));
            }
            #pragma unroll
            for (int np = 0; np < 8; np++) {
                const int off = (kk + (lane & 15)) * VSTR + np * 16 + (lane >> 4) * 8;
                unsigned b0[2], b1[2];
                ldsm4t(b0[0], b0[1], b1[0], b1[1], smem_u32(&sVh[off]));
                mma16816(acc_o[np*2],   ah, b0);
                mma16816(acc_o[np*2],   al, b0);
                mma16816(acc_o[np*2+1], ah, b1);
                mma16816(acc_o[np*2+1], al, b1);
                ldsm4t(b0[0], b0[1], b1[0], b1[1], smem_u32(&sVl[off]));
                mma16816(acc_o[np*2],   ah, b0);
                mma16816(acc_o[np*2+1], ah, b1);
            }
        }
    }

    // ---- epilogue: normalize, write hi/lo ao ----
    float l0 = l_r[0];
    l0 += __shfl_xor_sync(0xffffffffu, l0, 1);
    l0 += __shfl_xor_sync(0xffffffffu, l0, 2);
    float l1 = l_r[1];
    l1 += __shfl_xor_sync(0xffffffffu, l1, 1);
    l1 += __shfl_xor_sync(0xffffffffu, l1, 2);
    const float inv0 = 1.0f / l0;
    const float inv1 = 1.0f / l1;

    #pragma unroll
    for (int nf = 0; nf < 16; nf++) {
        const int col = nf * 8 + t * 2;
        const long o0 = (long)(b * TT + qi0) * (HH * DH) + h * DH + col;
        const long o1 = (long)(b * TT + qi1) * (HH * DH) + h * DH + col;
        split2(aoh + o0, aol + o0, acc_o[nf][0] * inv0, acc_o[nf][1] * inv0);
        split2(aoh + o1, aol + o1, acc_o[nf][2] * inv1, acc_o[nf][3] * inv1);
    }
}

// ---------------- 64x64 fp32 SGEMM (W_KR, N=64) ----------------
#define BM 64
#define BN 64
#define BKT 16

__global__ __launch_bounds__(256)
void sgemm_kernel(const float* __restrict__ A,
                  const float* __restrict__ Bp,
                  float* __restrict__ C,
                  int lda, int ldb, int ldc, int K)
{
    const int row0 = blockIdx.y * BM;
    const int col0 = blockIdx.x * BN;

    __shared__ float As[BKT][BM];
    __shared__ float Bs[BKT][BN];

    const int tid = threadIdx.x;
    const int tx = tid & 15, ty = tid >> 4;
    const int arow = tid >> 2,  acol = (tid & 3) * 4;
    const int brow = tid >> 4,  bcol = (tid & 15) * 4;

    float acc[4][4] = {};

    for (int k0 = 0; k0 < K; k0 += BKT) {
        float4 av = *(const float4*)(A + (long)(row0 + arow) * lda + k0 + acol);
        As[acol + 0][arow] = av.x;
        As[acol + 1][arow] = av.y;
        As[acol + 2][arow] = av.z;
        As[acol + 3][arow] = av.w;
        float4 bv = *(const float4*)(Bp + (long)(k0 + brow) * ldb + col0 + bcol);
        *(float4*)&Bs[brow][bcol] = bv;
        __syncthreads();
        #pragma unroll
        for (int kk = 0; kk < BKT; kk++) {
            float4 af = *(const float4*)&As[kk][ty * 4];
            float4 bf = *(const float4*)&Bs[kk][tx * 4];
            float a0[4] = {af.x, af.y, af.z, af.w};
            float b0[4] = {bf.x, bf.y, bf.z, bf.w};
            #pragma unroll
            for (int i = 0; i < 4; i++)
                #pragma unroll
                for (int j = 0; j < 4; j++)
                    acc[i][j] = fmaf(a0[i], b0[j], acc[i][j]);
        }
        __syncthreads();
    }

    #pragma unroll
    for (int i = 0; i < 4; i++) {
        const int r = row0 + ty * 4 + i;
        #pragma unroll
        for (int j = 0; j < 4; j++)
            C[(long)r * ldc + col0 + tx * 4 + j] = acc[i][j];
    }
}

// ---------------- RMSNorm: fp32 in -> hi/lo bf16 out ----------------
__global__ __launch_bounds__(256)
void rmsnorm16_kernel(const float* __restrict__ x, const float* __restrict__ w,
                      bf16* __restrict__ hi, bf16* __restrict__ lo, int len)
{
    const float* p = x + (long)blockIdx.x * len;
    bf16* ph = hi + (long)blockIdx.x * len;
    bf16* pl = lo + (long)blockIdx.x * len;
    __shared__ float red[256];
    const int tid = threadIdx.x;
    float s = 0.f;
    for (int i = tid; i < len; i += 256) { float v = p[i]; s += v * v; }
    red[tid] = s; __syncthreads();
    for (int d = 128; d > 0; d >>= 1) { if (tid < d) red[tid] += red[tid + d]; __syncthreads(); }
    const float inv = rsqrtf(red[0] / (float)len + EPS);
    for (int i = tid; i < len; i += 256)
        split1(ph + i, pl + i, p[i] * inv * w[i]);
}

// ---------------- RoPE q: fp32 staging -> hi/lo into qh/ql ----------------
__global__ void rope_q16_kernel(const float* __restrict__ qf,
                                bf16* __restrict__ qh, bf16* __restrict__ ql)
{
    long idx = (long)blockIdx.x * blockDim.x + threadIdx.x;   // B*T*H*32
    if (idx >= (long)NTOK * HH * 32) return;
    const int i = idx & 31;
    const int h = (idx >> 5) & 15;
    const long tok = idx >> 9;
    const int t = (int)(tok & (TT - 1));
    const float inv = powf(500000.0f, -(float)i / 32.0f);
    float c, s;
    sincosf((float)t * inv, &s, &c);
    const long off = tok * (HH * DQK) + (long)h * DQK + DH;
    const float a = qf[off + i], b = qf[off + i + 32];
    split1(qh + off + i,      ql + off + i,      a * c - b * s);
    split1(qh + off + i + 32, ql + off + i + 32, b * c + a * s);
}

// ---------------- RoPE k_R + broadcast into kh/kl for all heads ----------------
__global__ void rope_k16_kernel(const float* __restrict__ kR,
                                bf16* __restrict__ kh, bf16* __restrict__ kl)
{
    long idx = (long)blockIdx.x * blockDim.x + threadIdx.x;   // B*T*32
    if (idx >= (long)NTOK * 32) return;
    const int i = idx & 31;
    const long tok = idx >> 5;
    const int t = (int)(tok & (TT - 1));
    const float inv = powf(500000.0f, -(float)i / 32.0f);
    float c, s;
    sincosf((float)t * inv, &s, &c);
    const float a = kR[tok * DR + i], b = kR[tok * DR + i + 32];
    const float r0 = a * c - b * s;
    const float r1 = b * c + a * s;
    bf16 r0h = __float2bfloat16(r0);
    bf16 r0l = __float2bfloat16(r0 - __bfloat162float(r0h));
    bf16 r1h = __float2bfloat16(r1);
    bf16 r1l = __float2bfloat16(r1 - __bfloat162float(r1h));
    const long base = tok * (HH * DQK) + DH;
    #pragma unroll
    for (int h = 0; h < HH; h++) {
        kh[base + (long)h * DQK + i]      = r0h;
        kl[base + (long)h * DQK + i]      = r0l;
        kh[base + (long)h * DQK + i + 32] = r1h;
        kl[base + (long)h * DQK + i + 32] = r1l;
    }
}

// ---------------- launch ----------------
extern "C" void kernel_launch(void* const* d_in, const int* in_sizes, int n_in,
                              void* d_out, int out_size)
{
    const float* x     = (const float*)d_in[0];
    const float* W_DQ  = (const float*)d_in[1];
    const float* W_UQ  = (const float*)d_in[2];
    const float* W_QR  = (const float*)d_in[3];
    const float* W_DKV = (const float*)d_in[4];
    const float* W_UK  = (const float*)d_in[5];
    const float* W_UV  = (const float*)d_in[6];
    const float* W_KR  = (const float*)d_in[7];
    const float* W_O   = (const float*)d_in[8];
    const float* qnw   = (const float*)d_in[9];
    const float* kvnw  = (const float*)d_in[10];
    float* out = (float*)d_out;

    float *cQ, *cKV, *qf, *kR;
    bf16 *xh, *xl, *wh, *wl, *cQh, *cQl, *cKVh, *cKVl;
    bf16 *qh, *ql, *kh, *kl, *vh, *vl, *aoh, *aol;
    cudaGetSymbolAddress((void**)&cQ,   g_cQ);
    cudaGetSymbolAddress((void**)&cKV,  g_cKV);
    cudaGetSymbolAddress((void**)&qf,   g_qf);
    cudaGetSymbolAddress((void**)&kR,   g_kR);
    cudaGetSymbolAddress((void**)&xh,   g_xh);
    cudaGetSymbolAddress((void**)&xl,   g_xl);
    cudaGetSymbolAddress((void**)&wh,   g_wh);
    cudaGetSymbolAddress((void**)&wl,   g_wl);
    cudaGetSymbolAddress((void**)&cQh,  g_cQh);
    cudaGetSymbolAddress((void**)&cQl,  g_cQl);
    cudaGetSymbolAddress((void**)&cKVh, g_cKVh);
    cudaGetSymbolAddress((void**)&cKVl, g_cKVl);
    cudaGetSymbolAddress((void**)&qh,   g_qh);
    cudaGetSymbolAddress((void**)&ql,   g_ql);
    cudaGetSymbolAddress((void**)&kh,   g_kh);
    cudaGetSymbolAddress((void**)&kl,   g_kl);
    cudaGetSymbolAddress((void**)&vh,   g_vh);
    cudaGetSymbolAddress((void**)&vl,   g_vl);
    cudaGetSymbolAddress((void**)&aoh,  g_aoh);
    cudaGetSymbolAddress((void**)&aol,  g_aol);

    // idempotent, no static guard (harness forbids them)
    cudaFuncSetAttribute(flash_kernel,
        cudaFuncAttributeMaxDynamicSharedMemorySize, FLASH_SMEM);

    const dim3 blk(256);
    #define SPLIT(src, h, l, n) \
        split_kernel<<<(unsigned)(((n)/4 + 255)/256), blk>>>(src, h, l, (long)(n))

    // 0) pre-split inputs and weights
    SPLIT(x,     xh,           xl,           (long)NTOK*DD);
    SPLIT(W_DQ,  wh + OFF_DQ,  wl + OFF_DQ,  (long)DD*DQ);
    SPLIT(W_UQ,  wh + OFF_UQ,  wl + OFF_UQ,  (long)DQ*HH*DH);
    SPLIT(W_QR,  wh + OFF_QR,  wl + OFF_QR,  (long)DQ*HH*DR);
    SPLIT(W_DKV, wh + OFF_DKV, wl + OFF_DKV, (long)DD*DKV);
    SPLIT(W_UK,  wh + OFF_UK,  wl + OFF_UK,  (long)DKV*HH*DH);
    SPLIT(W_UV,  wh + OFF_UV,  wl + OFF_UV,  (long)DKV*HH*DH);
    SPLIT(W_O,   wh + OFF_O,   wl + OFF_O,   (long)HH*DH*DD);

    // 1) c_Q = x @ W_DQ ; RMSNorm -> hi/lo
    bgemm16_kernel<<<dim3(DQ/128, NTOK/128, 1), blk>>>(
        xh, xl, 0, 0, wh + OFF_DQ, wl + OFF_DQ, 0, 0,
        cQ, nullptr, nullptr, 0, 0, 1, DD, DQ, DQ, DD, 0, 0, 0);
    rmsnorm16_kernel<<<NTOK, blk>>>(cQ, qnw, cQh, cQl, DQ);

    // 2) c_KV = x @ W_DKV ; RMSNorm -> hi/lo
    bgemm16_kernel<<<dim3(DKV/128, NTOK/128, 1), blk>>>(
        xh, xl, 0, 0, wh + OFF_DKV, wl + OFF_DKV, 0, 0,
        cKV, nullptr, nullptr, 0, 0, 1, DD, DKV, DKV, DD, 0, 0, 0);
    rmsnorm16_kernel<<<NTOK, blk>>>(cKV, kvnw, cKVh, cKVl, DKV);

    // 3) q content -> qh/ql (remap); q rope -> fp32 staging
    bgemm16_kernel<<<dim3((HH*DH)/128, NTOK/128, 1), blk>>>(
        cQh, cQl, 0, 0, wh + OFF_UQ, wl + OFF_UQ, 0, 0,
        nullptr, qh, ql, 0, 0, 1, DQ, HH*DH, HH*DQK, DQ, DH, 0, 0);
    bgemm16_kernel<<<dim3((HH*DR)/128, NTOK/128, 1), blk>>>(
        cQh, cQl, 0, 0, wh + OFF_QR, wl + OFF_QR, 0, 0,
        qf, nullptr, nullptr, 0, 0, 1, DQ, HH*DR, HH*DQK, DQ, DR, DH, 0);

    // 4) k content -> kh/kl (remap); v -> vh/vl
    bgemm16_kernel<<<dim3((HH*DH)/128, NTOK/128, 1), blk>>>(
        cKVh, cKVl, 0, 0, wh + OFF_UK, wl + OFF_UK, 0, 0,
        nullptr, kh, kl, 0, 0, 1, DKV, HH*DH, HH*DQK, DKV, DH, 0, 0);
    bgemm16_kernel<<<dim3((HH*DH)/128, NTOK/128, 1), blk>>>(
        cKVh, cKVl, 0, 0, wh + OFF_UV, wl + OFF_UV, 0, 0,
        nullptr, vh, vl, 0, 0, 1, DKV, HH*DH, HH*DH, DKV, 0, 0, 0);

    // 5) k_R = x @ W_KR (fp32)
    sgemm_kernel<<<dim3(DR/64, NTOK/64), blk>>>(x, W_KR, kR, DD, DR, DR, DD);

    // 6) RoPE -> hi/lo
    rope_q16_kernel<<<(unsigned)(((long)NTOK*HH*32 + 255)/256), blk>>>(qf, qh, ql);
    rope_k16_kernel<<<(unsigned)(((long)NTOK*32 + 255)/256), blk>>>(kR, kh, kl);

    // 7) fused flash attention -> aoh/aol
    flash_kernel<<<dim3(BHZ, TT/128), blk, FLASH_SMEM>>>(
        qh, ql, kh, kl, vh, vl, aoh, aol);

    // 8) final: out = ao @ W_O (fp32 out)
    bgemm16_kernel<<<dim3(DD/128, NTOK/128, 1), blk>>>(
        aoh, aol, 0, 0, wh + OFF_O, wl + OFF_O, 0, 0,
        out, nullptr, nullptr, 0, 0, 1, HH*DH, DD, DD, HH*DH, 0, 0, 0);
}

// round 17
// speedup vs baseline: 1.2179x; 1.1565x over previous
#include <cuda_runtime.h>
#include <cuda_bf16.h>
#include <cstdint>
#include <math.h>

// ---------------- problem constants ----------------
#define BATCH 2
#define TT    2048
#define DD    2048
#define HH    16
#define DH    128
#define DKV   512
#define DQ    1024
#define DR    64
#define DQK   192            // DH + DR
#define NTOK  (BATCH*TT)     // 4096
#define BHZ   (BATCH*HH)     // 32
#define EPS   1e-6f
#define SCALE 0.072168783648703220563f   // 1/sqrt(192)

typedef __nv_bfloat16 bf16;

// ---------------- weight arena offsets (elements) ----------------
#define OFF_DQ  0L
#define OFF_UQ  2097152L
#define OFF_QR  4194304L
#define OFF_DKV 5242880L
#define OFF_UK  6291456L
#define OFF_UV  7340032L
#define OFF_O   8388608L
#define W_TOTAL 12582912L

// ---------------- scratch (device globals; allocation-free) ----------------
__device__ __align__(16) float g_cQ  [(size_t)NTOK * DQ];
__device__ __align__(16) float g_cKV [(size_t)NTOK * DKV];
__device__ __align__(16) float g_qf  [(size_t)NTOK * HH * DQK];
__device__ __align__(16) float g_kR  [(size_t)NTOK * DR];

__device__ __align__(16) bf16 g_xh  [(size_t)NTOK * DD];
__device__ __align__(16) bf16 g_xl  [(size_t)NTOK * DD];
__device__ __align__(16) bf16 g_wh  [W_TOTAL];
__device__ __align__(16) bf16 g_wl  [W_TOTAL];
__device__ __align__(16) bf16 g_cQh [(size_t)NTOK * DQ];
__device__ __align__(16) bf16 g_cQl [(size_t)NTOK * DQ];
__device__ __align__(16) bf16 g_cKVh[(size_t)NTOK * DKV];
__device__ __align__(16) bf16 g_cKVl[(size_t)NTOK * DKV];
__device__ __align__(16) bf16 g_qh  [(size_t)NTOK * HH * DQK];
__device__ __align__(16) bf16 g_ql  [(size_t)NTOK * HH * DQK];
__device__ __align__(16) bf16 g_kh  [(size_t)NTOK * HH * DQK];
__device__ __align__(16) bf16 g_kl  [(size_t)NTOK * HH * DQK];
__device__ __align__(16) bf16 g_vh  [(size_t)NTOK * HH * DH];
__device__ __align__(16) bf16 g_vl  [(size_t)NTOK * HH * DH];
__device__ __align__(16) bf16 g_aoh [(size_t)NTOK * HH * DH];
__device__ __align__(16) bf16 g_aol [(size_t)NTOK * HH * DH];

// =====================================================================
// helpers
// =====================================================================
#define ASTR 40
#define BSTR 136

__device__ __forceinline__ unsigned smem_u32(const void* p) {
    return (unsigned)__cvta_generic_to_shared(p);
}
__device__ __forceinline__ void ldsm4(unsigned& r0, unsigned& r1,
                                      unsigned& r2, unsigned& r3, unsigned a) {
    asm volatile("ldmatrix.sync.aligned.m8n8.x4.shared.b16 {%0,%1,%2,%3}, [%4];"
                 : "=r"(r0), "=r"(r1), "=r"(r2), "=r"(r3) : "r"(a));
}
__device__ __forceinline__ void ldsm4t(unsigned& r0, unsigned& r1,
                                       unsigned& r2, unsigned& r3, unsigned a) {
    asm volatile("ldmatrix.sync.aligned.m8n8.x4.trans.shared.b16 {%0,%1,%2,%3}, [%4];"
                 : "=r"(r0), "=r"(r1), "=r"(r2), "=r"(r3) : "r"(a));
}
__device__ __forceinline__ void mma16816(float* d, const unsigned* a, const unsigned* b) {
    asm volatile("mma.sync.aligned.m16n8k16.row.col.f32.bf16.bf16.f32 "
                 "{%0,%1,%2,%3}, {%4,%5,%6,%7}, {%8,%9}, {%0,%1,%2,%3};"
                 : "+f"(d[0]), "+f"(d[1]), "+f"(d[2]), "+f"(d[3])
                 : "r"(a[0]), "r"(a[1]), "r"(a[2]), "r"(a[3]),
                   "r"(b[0]), "r"(b[1]));
}
__device__ __forceinline__ void split1(bf16* hp, bf16* lp, float v) {
    bf16 h = __float2bfloat16(v);
    *hp = h;
    *lp = __float2bfloat16(v - __bfloat162float(h));
}
__device__ __forceinline__ void split2(bf16* hp, bf16* lp, float v0, float v1) {
    __nv_bfloat162 h, l;
    h.x = __float2bfloat16(v0);
    h.y = __float2bfloat16(v1);
    l.x = __float2bfloat16(v0 - __bfloat162float(h.x));
    l.y = __float2bfloat16(v1 - __bfloat162float(h.y));
    *(__nv_bfloat162*)hp = h;
    *(__nv_bfloat162*)lp = l;
}
__device__ __forceinline__ void cpa16(unsigned d, const void* s) {
    asm volatile("cp.async.cg.shared.global [%0], [%1], 16;" :: "r"(d), "l"(s));
}
__device__ __forceinline__ void cp_commit() {
    asm volatile("cp.async.commit_group;");
}
__device__ __forceinline__ void cp_wait0() {
    asm volatile("cp.async.wait_group 0;");
}
__device__ __forceinline__ void cp_wait1() {
    asm volatile("cp.async.wait_group 1;");
}

// ---------------- fp32 -> hi/lo bf16 split (elementwise) ----------------
__global__ void split_kernel(const float* __restrict__ src,
                             bf16* __restrict__ hi, bf16* __restrict__ lo, long n)
{
    long i = ((long)blockIdx.x * blockDim.x + threadIdx.x) * 4;
    if (i >= n) return;
    float4 v = *(const float4*)(src + i);
    split2(hi + i, lo + i, v.x, v.y);
    split2(hi + i + 2, lo + i + 2, v.z, v.w);
}

// =====================================================================
// Batched tensor-core GEMM on pre-split bf16 hi/lo operands,
// 2-stage cp.async pipeline, dynamic smem (2 stages x 37.9 KB).
// =====================================================================
#define BG_SA (128 * ASTR)
#define BG_SB (32 * BSTR)
#define BG_STG (2 * BG_SA + 2 * BG_SB)
#define BG_SMEM (2 * BG_STG * 2)      // bytes

__global__ __launch_bounds__(256, 2)
void bgemm16_kernel(const bf16* __restrict__ Ah, const bf16* __restrict__ Al,
                    long Ao, long Ai,
                    const bf16* __restrict__ Bh, const bf16* __restrict__ Bl,
                    long Bo, long Bi,
                    float* __restrict__ C, bf16* __restrict__ Ch, bf16* __restrict__ Cl,
                    long Co, long Ci,
                    int zmod, int lda, int ldb, int ldc,
                    int K, int head_in, int head_off, int causal)
{
    extern __shared__ __align__(16) bf16 dynsm[];

    const int z = blockIdx.z;
    const long zb = (long)(z / zmod), zi = (long)(z % zmod);
    const bf16* Ahb = Ah + zb * Ao + zi * Ai;
    const bf16* Alb = Al + zb * Ao + zi * Ai;
    const bf16* Bhb = Bh + zb * Bo + zi * Bi;
    const bf16* Blb = Bl + zb * Bo + zi * Bi;

    const int tid = threadIdx.x;
    const int wid = tid >> 5, lane = tid & 31;
    const int wm = (wid & 1) * 64;
    const int wn = (wid >> 1) * 32;
    const int row0 = blockIdx.y * 128;
    const int col0 = blockIdx.x * 128;
    const int Keff = causal ? min(K, (int)(blockIdx.y + 1) * 128) : K;
    const int nIt = Keff >> 5;

    // per-thread load coords (constant across stages)
    const int af0 = tid * 2, ar0 = af0 >> 2, ac0 = (af0 & 3) * 8;
    const int af1 = af0 + 1, ar1 = af1 >> 2, ac1 = (af1 & 3) * 8;
    const int br0 = af0 >> 4, bc0 = (af0 & 15) * 8;
    const int br1 = af1 >> 4, bc1 = (af1 & 15) * 8;

    float acc[4][4][4];
    #pragma unroll
    for (int i = 0; i < 4; i++)
        #pragma unroll
        for (int j = 0; j < 4; j++)
            #pragma unroll
            for (int r = 0; r < 4; r++) acc[i][j][r] = 0.f;

    // stage load: issue 8 cp.async per thread, one commit
    auto load_stage = [&](int s, int k0) {
        bf16* pAh = dynsm + (long)s * BG_STG;
        bf16* pAl = pAh + BG_SA;
        bf16* pBh = pAl + BG_SA;
        bf16* pBl = pBh + BG_SB;
        long gi;
        gi = (long)(row0 + ar0) * lda + k0 + ac0;
        cpa16(smem_u32(&pAh[ar0 * ASTR + ac0]), Ahb + gi);
        cpa16(smem_u32(&pAl[ar0 * ASTR + ac0]), Alb + gi);
        gi = (long)(row0 + ar1) * lda + k0 + ac1;
        cpa16(smem_u32(&pAh[ar1 * ASTR + ac1]), Ahb + gi);
        cpa16(smem_u32(&pAl[ar1 * ASTR + ac1]), Alb + gi);
        gi = (long)(k0 + br0) * ldb + col0 + bc0;
        cpa16(smem_u32(&pBh[br0 * BSTR + bc0]), Bhb + gi);
        cpa16(smem_u32(&pBl[br0 * BSTR + bc0]), Blb + gi);
        gi = (long)(k0 + br1) * ldb + col0 + bc1;
        cpa16(smem_u32(&pBh[br1 * BSTR + bc1]), Bhb + gi);
        cpa16(smem_u32(&pBl[br1 * BSTR + bc1]), Blb + gi);
        cp_commit();
    };

    load_stage(0, 0);

    for (int it = 0; it < nIt; it++) {
        if (it + 1 < nIt) {
            load_stage((it + 1) & 1, (it + 1) * 32);
            cp_wait1();
        } else {
            cp_wait0();
        }
        __syncthreads();

        bf16* pAh = dynsm + (long)(it & 1) * BG_STG;
        bf16* pAl = pAh + BG_SA;
        bf16* pBh = pAl + BG_SA;
        bf16* pBl = pBh + BG_SB;

        #pragma unroll
        for (int kk = 0; kk < 32; kk += 16) {
            unsigned ah[4][4], al[4][4], bh[4][2], bl[4][2];
            #pragma unroll
            for (int mi = 0; mi < 4; mi++) {
                const int off = (wm + mi * 16 + (lane & 15)) * ASTR + kk + (lane >> 4) * 8;
                ldsm4(ah[mi][0], ah[mi][1], ah[mi][2], ah[mi][3], smem_u32(&pAh[off]));
                ldsm4(al[mi][0], al[mi][1], al[mi][2], al[mi][3], smem_u32(&pAl[off]));
            }
            #pragma unroll
            for (int np = 0; np < 2; np++) {
                const int off = (kk + (lane & 15)) * BSTR + wn + np * 16 + (lane >> 4) * 8;
                ldsm4t(bh[np*2][0], bh[np*2][1], bh[np*2+1][0], bh[np*2+1][1],
                       smem_u32(&pBh[off]));
                ldsm4t(bl[np*2][0], bl[np*2][1], bl[np*2+1][0], bl[np*2+1][1],
                       smem_u32(&pBl[off]));
            }
            #pragma unroll
            for (int mi = 0; mi < 4; mi++)
                #pragma unroll
                for (int nj = 0; nj < 4; nj++) {
                    mma16816(acc[mi][nj], ah[mi], bh[nj]);
                    mma16816(acc[mi][nj], ah[mi], bl[nj]);
                    mma16816(acc[mi][nj], al[mi], bh[nj]);
                }
        }
        __syncthreads();
    }

    const int g = lane >> 2, t = lane & 3;
    #pragma unroll
    for (int mi = 0; mi < 4; mi++) {
        #pragma unroll
        for (int nj = 0; nj < 4; nj++) {
            const int c = col0 + wn + nj * 8 + t * 2;
            const int oc = (head_in > 0)
                ? (c / head_in) * DQK + head_off + (c % head_in) : c;
            #pragma unroll
            for (int rr = 0; rr < 2; rr++) {
                const int r = row0 + wm + mi * 16 + g + rr * 8;
                const long zo = zb * Co + zi * Ci + (long)r * ldc + oc;
                const float v0 = acc[mi][nj][rr * 2 + 0];
                const float v1 = acc[mi][nj][rr * 2 + 1];
                if (Ch) split2(Ch + zo, Cl + zo, v0, v1);
                else    *(float2*)(C + zo) = make_float2(v0, v1);
            }
        }
    }
}

// =====================================================================
// Fused flash attention with cp.async tile loads.
// One CTA per (z, q-tile of 128). 8 warps; warp w owns q-rows w*16..w*16+15.
// =====================================================================
#define QSTR 200
#define KSTR 200
#define VSTR 136
#define PSTR 72
#define FLASH_SMEM ((2*128*QSTR + 2*64*KSTR + 2*64*VSTR + 2*128*PSTR) * 2)

__global__ __launch_bounds__(256)
void flash_kernel(const bf16* __restrict__ qh, const bf16* __restrict__ ql,
                  const bf16* __restrict__ kh, const bf16* __restrict__ kl,
                  const bf16* __restrict__ vh, const bf16* __restrict__ vl,
                  bf16* __restrict__ aoh, bf16* __restrict__ aol)
{
    extern __shared__ __align__(16) bf16 smem[];
    bf16* sQh = smem;
    bf16* sQl = sQh + 128 * QSTR;
    bf16* sKh = sQl + 128 * QSTR;
    bf16* sKl = sKh + 64 * KSTR;
    bf16* sVh = sKl + 64 * KSTR;
    bf16* sVl = sVh + 64 * VSTR;
    bf16* sPh = sVl + 64 * VSTR;
    bf16* sPl = sPh + 128 * PSTR;

    const int qt = (int)gridDim.y - 1 - (int)blockIdx.y;   // big tiles first
    const int z  = blockIdx.x;
    const int b = z >> 4, h = z & 15;
    const int q0 = qt * 128;
    const long qkbase = (long)b * TT * (HH * DQK) + (long)h * DQK;
    const long vbase  = (long)b * TT * (HH * DH) + (long)h * DH;

    const int tid = threadIdx.x;
    const int wid = tid >> 5, lane = tid & 31;
    const int g = lane >> 2, t = lane & 3;
    const int wq = wid * 16;

    // load Q tile (128 x 192, hi+lo) via cp.async (own group; drained by first wait0)
    for (int i = tid; i < 3072; i += 256) {
        const int r = i / 24;
        const int c = (i % 24) * 8;
        const long gi = qkbase + (long)(q0 + r) * (HH * DQK) + c;
        cpa16(smem_u32(&sQh[r * QSTR + c]), qh + gi);
        cpa16(smem_u32(&sQl[r * QSTR + c]), ql + gi);
    }
    cp_commit();

    float m_r[2] = {-1e30f, -1e30f};
    float l_r[2] = {0.f, 0.f};
    float acc_o[16][4];
    #pragma unroll
    for (int i = 0; i < 16; i++)
        #pragma unroll
        for (int r = 0; r < 4; r++) acc_o[i][r] = 0.f;

    const int qi0 = q0 + wq + g;       // thread's two rows
    const int qi1 = qi0 + 8;
    const int nkt = 2 * qt + 2;

    for (int kt = 0; kt < nkt; kt++) {
        const int k0 = kt * 64;
        __syncthreads();               // protect prior K/V use
        // load K tile (64 x 192) + V tile (64 x 128) via cp.async
        for (int i = tid; i < 1536; i += 256) {
            const int r = i / 24;
            const int c = (i % 24) * 8;
            const long gi = qkbase + (long)(k0 + r) * (HH * DQK) + c;
            cpa16(smem_u32(&sKh[r * KSTR + c]), kh + gi);
            cpa16(smem_u32(&sKl[r * KSTR + c]), kl + gi);
        }
        for (int i = tid; i < 1024; i += 256) {
            const int r = i / 16;
            const int c = (i % 16) * 8;
            const long gi = vbase + (long)(k0 + r) * (HH * DH) + c;
            cpa16(smem_u32(&sVh[r * VSTR + c]), vh + gi);
            cpa16(smem_u32(&sVl[r * VSTR + c]), vl + gi);
        }
        cp_commit();
        cp_wait0();
        __syncthreads();

        // ---- S = Q K^T (warp rows wq..wq+15, cols 0..63) ----
        float s[8][4];
        #pragma unroll
        for (int i = 0; i < 8; i++)
            #pragma unroll
            for (int r = 0; r < 4; r++) s[i][r] = 0.f;

        #pragma unroll
        for (int d0 = 0; d0 < DQK; d0 += 16) {
            unsigned ah[4], al[4];
            {
                const int off = (wq + (lane & 15)) * QSTR + d0 + (lane >> 4) * 8;
                ldsm4(ah[0], ah[1], ah[2], ah[3], smem_u32(&sQh[off]));
                ldsm4(al[0], al[1], al[2], al[3], smem_u32(&sQl[off]));
            }
            #pragma unroll
            for (int np = 0; np < 4; np++) {
                const int off = (np * 16 + (lane & 15)) * KSTR + d0 + (lane >> 4) * 8;
                unsigned r0, r1, r2, r3;
                unsigned b0[2], b1[2];
                ldsm4(r0, r1, r2, r3, smem_u32(&sKh[off]));
                b0[0] = r0; b0[1] = r2;
                b1[0] = r1; b1[1] = r3;
                mma16816(s[np*2],   ah, b0);
                mma16816(s[np*2],   al, b0);
                mma16816(s[np*2+1], ah, b1);
                mma16816(s[np*2+1], al, b1);
                ldsm4(r0, r1, r2, r3, smem_u32(&sKl[off]));
                b0[0] = r0; b0[1] = r2;
                b1[0] = r1; b1[1] = r3;
                mma16816(s[np*2],   ah, b0);
                mma16816(s[np*2+1], ah, b1);
            }
        }

        // ---- scale + causal mask + tile row-max ----
        const bool diag = (k0 + 63 > q0 + wq);
        float mt0 = -1e30f, mt1 = -1e30f;
        #pragma unroll
        for (int nf = 0; nf < 8; nf++) {
            #pragma unroll
            for (int e = 0; e < 2; e++) {
                const int kj = k0 + nf * 8 + t * 2 + e;
                float v0 = s[nf][e]     * SCALE;
                float v1 = s[nf][2 + e] * SCALE;
                if (diag) {
                    if (kj > qi0) v0 = -1e30f;
                    if (kj > qi1) v1 = -1e30f;
                }
                s[nf][e] = v0; s[nf][2 + e] = v1;
                mt0 = fmaxf(mt0, v0); mt1 = fmaxf(mt1, v1);
            }
        }
        mt0 = fmaxf(mt0, __shfl_xor_sync(0xffffffffu, mt0, 1));
        mt0 = fmaxf(mt0, __shfl_xor_sync(0xffffffffu, mt0, 2));
        mt1 = fmaxf(mt1, __shfl_xor_sync(0xffffffffu, mt1, 1));
        mt1 = fmaxf(mt1, __shfl_xor_sync(0xffffffffu, mt1, 2));

        const float mn0 = fmaxf(m_r[0], mt0);
        const float mn1 = fmaxf(m_r[1], mt1);
        const float a0 = __expf(m_r[0] - mn0);
        const float a1 = __expf(m_r[1] - mn1);
        m_r[0] = mn0; m_r[1] = mn1;
        l_r[0] *= a0; l_r[1] *= a1;
        #pragma unroll
        for (int nf = 0; nf < 16; nf++) {
            acc_o[nf][0] *= a0; acc_o[nf][1] *= a0;
            acc_o[nf][2] *= a1; acc_o[nf][3] *= a1;
        }

        // ---- P = exp(S - m), write hi/lo to smem ----
        #pragma unroll
        for (int nf = 0; nf < 8; nf++) {
            const float p00 = __expf(s[nf][0] - mn0);
            const float p01 = __expf(s[nf][1] - mn0);
            const float p10 = __expf(s[nf][2] - mn1);
            const float p11 = __expf(s[nf][3] - mn1);
            l_r[0] += p00 + p01;
            l_r[1] += p10 + p11;
            const int cb = nf * 8 + t * 2;
            split2(&sPh[(wq + g) * PSTR + cb],     &sPl[(wq + g) * PSTR + cb],     p00, p01);
            split2(&sPh[(wq + g + 8) * PSTR + cb], &sPl[(wq + g + 8) * PSTR + cb], p10, p11);
        }
        __syncwarp();

        // ---- O += P (16x64) * V (64x128) ----
        #pragma unroll
        for (int kk = 0; kk < 64; kk += 16) {
            unsigned ah[4], al[4];
            {
                const int off = (wq + (lane & 15)) * PSTR + kk + (lane >> 4) * 8;
                ldsm4(ah[0], ah[1], ah[2], ah[3], smem_u32(&sPh[off]));
                ldsm4(al[0], al[1], al[2], al[3], smem_u32(&sPl[off]));
            }
            #pragma unroll
            for (int np = 0; np < 8; np++) {
                const int off = (kk + (lane & 15)) * VSTR + np * 16 + (lane >> 4) * 8;
                unsigned b0[2], b1[2];
                ldsm4t(b0[0], b0[1], b1[0], b1[1], smem_u32(&sVh[off]));
                mma16816(acc_o[np*2],   ah, b0);
                mma16816(acc_o[np*2],   al, b0);
                mma16816(acc_o[np*2+1], ah, b1);
                mma16816(acc_o[np*2+1], al, b1);
                ldsm4t(b0[0], b0[1], b1[0], b1[1], smem_u32(&sVl[off]));
                mma16816(acc_o[np*2],   ah, b0);
                mma16816(acc_o[np*2+1], ah, b1);
            }
        }
    }

    // ---- epilogue: normalize, write hi/lo ao ----
    float l0 = l_r[0];
    l0 += __shfl_xor_sync(0xffffffffu, l0, 1);
    l0 += __shfl_xor_sync(0xffffffffu, l0, 2);
    float l1 = l_r[1];
    l1 += __shfl_xor_sync(0xffffffffu, l1, 1);
    l1 += __shfl_xor_sync(0xffffffffu, l1, 2);
    const float inv0 = 1.0f / l0;
    const float inv1 = 1.0f / l1;

    #pragma unroll
    for (int nf = 0; nf < 16; nf++) {
        const int col = nf * 8 + t * 2;
        const long o0 = (long)(b * TT + qi0) * (HH * DH) + h * DH + col;
        const long o1 = (long)(b * TT + qi1) * (HH * DH) + h * DH + col;
        split2(aoh + o0, aol + o0, acc_o[nf][0] * inv0, acc_o[nf][1] * inv0);
        split2(aoh + o1, aol + o1, acc_o[nf][2] * inv1, acc_o[nf][3] * inv1);
    }
}

// ---------------- 64x64 fp32 SGEMM (W_KR, N=64) ----------------
#define BM 64
#define BN 64
#define BKT 16

__global__ __launch_bounds__(256)
void sgemm_kernel(const float* __restrict__ A,
                  const float* __restrict__ Bp,
                  float* __restrict__ C,
                  int lda, int ldb, int ldc, int K)
{
    const int row0 = blockIdx.y * BM;
    const int col0 = blockIdx.x * BN;

    __shared__ float As[BKT][BM];
    __shared__ float Bs[BKT][BN];

    const int tid = threadIdx.x;
    const int tx = tid & 15, ty = tid >> 4;
    const int arow = tid >> 2,  acol = (tid & 3) * 4;
    const int brow = tid >> 4,  bcol = (tid & 15) * 4;

    float acc[4][4] = {};

    for (int k0 = 0; k0 < K; k0 += BKT) {
        float4 av = *(const float4*)(A + (long)(row0 + arow) * lda + k0 + acol);
        As[acol + 0][arow] = av.x;
        As[acol + 1][arow] = av.y;
        As[acol + 2][arow] = av.z;
        As[acol + 3][arow] = av.w;
        float4 bv = *(const float4*)(Bp + (long)(k0 + brow) * ldb + col0 + bcol);
        *(float4*)&Bs[brow][bcol] = bv;
        __syncthreads();
        #pragma unroll
        for (int kk = 0; kk < BKT; kk++) {
            float4 af = *(const float4*)&As[kk][ty * 4];
            float4 bf = *(const float4*)&Bs[kk][tx * 4];
            float a0[4] = {af.x, af.y, af.z, af.w};
            float b0[4] = {bf.x, bf.y, bf.z, bf.w};
            #pragma unroll
            for (int i = 0; i < 4; i++)
                #pragma unroll
                for (int j = 0; j < 4; j++)
                    acc[i][j] = fmaf(a0[i], b0[j], acc[i][j]);
        }
        __syncthreads();
    }

    #pragma unroll
    for (int i = 0; i < 4; i++) {
        const int r = row0 + ty * 4 + i;
        #pragma unroll
        for (int j = 0; j < 4; j++)
            C[(long)r * ldc + col0 + tx * 4 + j] = acc[i][j];
    }
}

// ---------------- RMSNorm: fp32 in -> hi/lo bf16 out ----------------
__global__ __launch_bounds__(256)
void rmsnorm16_kernel(const float* __restrict__ x, const float* __restrict__ w,
                      bf16* __restrict__ hi, bf16* __restrict__ lo, int len)
{
    const float* p = x + (long)blockIdx.x * len;
    bf16* ph = hi + (long)blockIdx.x * len;
    bf16* pl = lo + (long)blockIdx.x * len;
    __shared__ float red[256];
    const int tid = threadIdx.x;
    float s = 0.f;
    for (int i = tid; i < len; i += 256) { float v = p[i]; s += v * v; }
    red[tid] = s; __syncthreads();
    for (int d = 128; d > 0; d >>= 1) { if (tid < d) red[tid] += red[tid + d]; __syncthreads(); }
    const float inv = rsqrtf(red[0] / (float)len + EPS);
    for (int i = tid; i < len; i += 256)
        split1(ph + i, pl + i, p[i] * inv * w[i]);
}

// ---------------- RoPE q: fp32 staging -> hi/lo into qh/ql ----------------
__global__ void rope_q16_kernel(const float* __restrict__ qf,
                                bf16* __restrict__ qh, bf16* __restrict__ ql)
{
    long idx = (long)blockIdx.x * blockDim.x + threadIdx.x;   // B*T*H*32
    if (idx >= (long)NTOK * HH * 32) return;
    const int i = idx & 31;
    const int h = (idx >> 5) & 15;
    const long tok = idx >> 9;
    const int t = (int)(tok & (TT - 1));
    const float inv = powf(500000.0f, -(float)i / 32.0f);
    float c, s;
    sincosf((float)t * inv, &s, &c);
    const long off = tok * (HH * DQK) + (long)h * DQK + DH;
    const float a = qf[off + i], b = qf[off + i + 32];
    split1(qh + off + i,      ql + off + i,      a * c - b * s);
    split1(qh + off + i + 32, ql + off + i + 32, b * c + a * s);
}

// ---------------- RoPE k_R + broadcast into kh/kl for all heads ----------------
__global__ void rope_k16_kernel(const float* __restrict__ kR,
                                bf16* __restrict__ kh, bf16* __restrict__ kl)
{
    long idx = (long)blockIdx.x * blockDim.x + threadIdx.x;   // B*T*32
    if (idx >= (long)NTOK * 32) return;
    const int i = idx & 31;
    const long tok = idx >> 5;
    const int t = (int)(tok & (TT - 1));
    const float inv = powf(500000.0f, -(float)i / 32.0f);
    float c, s;
    sincosf((float)t * inv, &s, &c);
    const float a = kR[tok * DR + i], b = kR[tok * DR + i + 32];
    const float r0 = a * c - b * s;
    const float r1 = b * c + a * s;
    bf16 r0h = __float2bfloat16(r0);
    bf16 r0l = __float2bfloat16(r0 - __bfloat162float(r0h));
    bf16 r1h = __float2bfloat16(r1);
    bf16 r1l = __float2bfloat16(r1 - __bfloat162float(r1h));
    const long base = tok * (HH * DQK) + DH;
    #pragma unroll
    for (int h = 0; h < HH; h++) {
        kh[base + (long)h * DQK + i]      = r0h;
        kl[base + (long)h * DQK + i]      = r0l;
        kh[base + (long)h * DQK + i + 32] = r1h;
        kl[base + (long)h * DQK + i + 32] = r1l;
    }
}

// ---------------- launch ----------------
extern "C" void kernel_launch(void* const* d_in, const int* in_sizes, int n_in,
                              void* d_out, int out_size)
{
    const float* x     = (const float*)d_in[0];
    const float* W_DQ  = (const float*)d_in[1];
    const float* W_UQ  = (const float*)d_in[2];
    const float* W_QR  = (const float*)d_in[3];
    const float* W_DKV = (const float*)d_in[4];
    const float* W_UK  = (const float*)d_in[5];
    const float* W_UV  = (const float*)d_in[6];
    const float* W_KR  = (const float*)d_in[7];
    const float* W_O   = (const float*)d_in[8];
    const float* qnw   = (const float*)d_in[9];
    const float* kvnw  = (const float*)d_in[10];
    float* out = (float*)d_out;

    float *cQ, *cKV, *qf, *kR;
    bf16 *xh, *xl, *wh, *wl, *cQh, *cQl, *cKVh, *cKVl;
    bf16 *qh, *ql, *kh, *kl, *vh, *vl, *aoh, *aol;
    cudaGetSymbolAddress((void**)&cQ,   g_cQ);
    cudaGetSymbolAddress((void**)&cKV,  g_cKV);
    cudaGetSymbolAddress((void**)&qf,   g_qf);
    cudaGetSymbolAddress((void**)&kR,   g_kR);
    cudaGetSymbolAddress((void**)&xh,   g_xh);
    cudaGetSymbolAddress((void**)&xl,   g_xl);
    cudaGetSymbolAddress((void**)&wh,   g_wh);
    cudaGetSymbolAddress((void**)&wl,   g_wl);
    cudaGetSymbolAddress((void**)&cQh,  g_cQh);
    cudaGetSymbolAddress((void**)&cQl,  g_cQl);
    cudaGetSymbolAddress((void**)&cKVh, g_cKVh);
    cudaGetSymbolAddress((void**)&cKVl, g_cKVl);
    cudaGetSymbolAddress((void**)&qh,   g_qh);
    cudaGetSymbolAddress((void**)&ql,   g_ql);
    cudaGetSymbolAddress((void**)&kh,   g_kh);
    cudaGetSymbolAddress((void**)&kl,   g_kl);
    cudaGetSymbolAddress((void**)&vh,   g_vh);
    cudaGetSymbolAddress((void**)&vl,   g_vl);
    cudaGetSymbolAddress((void**)&aoh,  g_aoh);
    cudaGetSymbolAddress((void**)&aol,  g_aol);

    // idempotent attribute sets (no static guards allowed)
    cudaFuncSetAttribute(flash_kernel,
        cudaFuncAttributeMaxDynamicSharedMemorySize, FLASH_SMEM);
    cudaFuncSetAttribute(bgemm16_kernel,
        cudaFuncAttributeMaxDynamicSharedMemorySize, BG_SMEM);

    const dim3 blk(256);
    #define SPLIT(src, h, l, n) \
        split_kernel<<<(unsigned)(((n)/4 + 255)/256), blk>>>(src, h, l, (long)(n))

    // 0) pre-split inputs and weights
    SPLIT(x,     xh,           xl,           (long)NTOK*DD);
    SPLIT(W_DQ,  wh + OFF_DQ,  wl + OFF_DQ,  (long)DD*DQ);
    SPLIT(W_UQ,  wh + OFF_UQ,  wl + OFF_UQ,  (long)DQ*HH*DH);
    SPLIT(W_QR,  wh + OFF_QR,  wl + OFF_QR,  (long)DQ*HH*DR);
    SPLIT(W_DKV, wh + OFF_DKV, wl + OFF_DKV, (long)DD*DKV);
    SPLIT(W_UK,  wh + OFF_UK,  wl + OFF_UK,  (long)DKV*HH*DH);
    SPLIT(W_UV,  wh + OFF_UV,  wl + OFF_UV,  (long)DKV*HH*DH);
    SPLIT(W_O,   wh + OFF_O,   wl + OFF_O,   (long)HH*DH*DD);

    // 1) c_Q = x @ W_DQ ; RMSNorm -> hi/lo
    bgemm16_kernel<<<dim3(DQ/128, NTOK/128, 1), blk, BG_SMEM>>>(
        xh, xl, 0, 0, wh + OFF_DQ, wl + OFF_DQ, 0, 0,
        cQ, nullptr, nullptr, 0, 0, 1, DD, DQ, DQ, DD, 0, 0, 0);
    rmsnorm16_kernel<<<NTOK, blk>>>(cQ, qnw, cQh, cQl, DQ);

    // 2) c_KV = x @ W_DKV ; RMSNorm -> hi/lo
    bgemm16_kernel<<<dim3(DKV/128, NTOK/128, 1), blk, BG_SMEM>>>(
        xh, xl, 0, 0, wh + OFF_DKV, wl + OFF_DKV, 0, 0,
        cKV, nullptr, nullptr, 0, 0, 1, DD, DKV, DKV, DD, 0, 0, 0);
    rmsnorm16_kernel<<<NTOK, blk>>>(cKV, kvnw, cKVh, cKVl, DKV);

    // 3) q content -> qh/ql (remap); q rope -> fp32 staging
    bgemm16_kernel<<<dim3((HH*DH)/128, NTOK/128, 1), blk, BG_SMEM>>>(
        cQh, cQl, 0, 0, wh + OFF_UQ, wl + OFF_UQ, 0, 0,
        nullptr, qh, ql, 0, 0, 1, DQ, HH*DH, HH*DQK, DQ, DH, 0, 0);
    bgemm16_kernel<<<dim3((HH*DR)/128, NTOK/128, 1), blk, BG_SMEM>>>(
        cQh, cQl, 0, 0, wh + OFF_QR, wl + OFF_QR, 0, 0,
        qf, nullptr, nullptr, 0, 0, 1, DQ, HH*DR, HH*DQK, DQ, DR, DH, 0);

    // 4) k content -> kh/kl (remap); v -> vh/vl
    bgemm16_kernel<<<dim3((HH*DH)/128, NTOK/128, 1), blk, BG_SMEM>>>(
        cKVh, cKVl, 0, 0, wh + OFF_UK, wl + OFF_UK, 0, 0,
        nullptr, kh, kl, 0, 0, 1, DKV, HH*DH, HH*DQK, DKV, DH, 0, 0);
    bgemm16_kernel<<<dim3((HH*DH)/128, NTOK/128, 1), blk, BG_SMEM>>>(
        cKVh, cKVl, 0, 0, wh + OFF_UV, wl + OFF_UV, 0, 0,
        nullptr, vh, vl, 0, 0, 1, DKV, HH*DH, HH*DH, DKV, 0, 0, 0);

    // 5) k_R = x @ W_KR (fp32)
    sgemm_kernel<<<dim3(DR/64, NTOK/64), blk>>>(x, W_KR, kR, DD, DR, DR, DD);

    // 6) RoPE -> hi/lo
    rope_q16_kernel<<<(unsigned)(((long)NTOK*HH*32 + 255)/256), blk>>>(qf, qh, ql);
    rope_k16_kernel<<<(unsigned)(((long)NTOK*32 + 255)/256), blk>>>(kR, kh, kl);

    // 7) fused flash attention -> aoh/aol
    flash_kernel<<<dim3(BHZ, TT/128), blk, FLASH_SMEM>>>(
        qh, ql, kh, kl, vh, vl, aoh, aol);

    // 8) final: out = ao @ W_O (fp32 out)
    bgemm16_kernel<<<dim3(DD/128, NTOK/128, 1), blk, BG_SMEM>>>(
        aoh, aol, 0, 0, wh + OFF_O, wl + OFF_O, 0, 0,
        out, nullptr, nullptr, 0, 0, 1, HH*DH, DD, DD, HH*DH, 0, 0, 0);
}